// round 11
// baseline (speedup 1.0000x reference)
#include <cuda_runtime.h>
#include <cuda_bf16.h>
#include <cstdint>

#define S 4096
#define D 256
#define L 4
#define E 4
#define V 32000
#define KGATE 2201   // int(4096 * sigmoid(0.15))

// ---------------- device scratch (no allocations allowed) ----------------
__device__ float g_x[S * D];            // fp32 activations
__device__ float g_y[S * E * D];        // all-expert outputs
__device__ float g_scores[S];
__device__ float g_mu[D];
__device__ float g_istd[D];
__device__ float g_absnb[D];
__device__ float g_thr[1];
__device__ float g_mask[S * E];
__device__ int   g_idx[S];              // permutation: kept rows first
__device__ int   g_keepf[S];            // keep flag per token
__device__ int   g_nk[1];               // number of kept tokens
__device__ float g_fill[V];             // head output row for dropped tokens
__device__ float g_psum[32][D], g_psum2[32][D];   // stats partials
__device__ __nv_bfloat16 g_xs0[S * D], g_xs1[S * D];   // LN'd x limbs (head A)
__device__ __nv_bfloat16 g_wh0[V * D], g_wh1[V * D];   // head W limbs

// ================= PTX helpers (sm_80-class, legal on plain sm_103) ==========
__device__ __forceinline__ uint32_t smem_u32(const void* p) {
    uint32_t a;
    asm("{ .reg .u64 t; cvta.to.shared.u64 t, %1; cvt.u32.u64 %0, t; }" : "=r"(a) : "l"(p));
    return a;
}
__device__ __forceinline__ void cp_async16(uint32_t s, const void* g) {
    asm volatile("cp.async.cg.shared.global [%0], [%1], 16;" :: "r"(s), "l"(g));
}
__device__ __forceinline__ void cp_commit() {
    asm volatile("cp.async.commit_group;");
}
template <int N>
__device__ __forceinline__ void cp_wait() {
    asm volatile("cp.async.wait_group %0;" :: "n"(N));
}
__device__ __forceinline__ uint32_t lds32(uint32_t addr) {
    uint32_t v;
    asm volatile("ld.shared.b32 %0, [%1];" : "=r"(v) : "r"(addr));
    return v;
}
__device__ __forceinline__ void mma16816(float* c, const uint32_t* a, const uint32_t* b) {
    asm volatile("mma.sync.aligned.m16n8k16.row.col.f32.bf16.bf16.f32 "
                 "{%0,%1,%2,%3}, {%4,%5,%6,%7}, {%8,%9}, {%0,%1,%2,%3};"
                 : "+f"(c[0]), "+f"(c[1]), "+f"(c[2]), "+f"(c[3])
                 : "r"(a[0]), "r"(a[1]), "r"(a[2]), "r"(a[3]), "r"(b[0]), "r"(b[1]));
}

// =============== head GEMM (proven R9: lds32 frags; row gather/scatter) =========
#define ROWB 144                        // 64 bf16 + pad = 144 B per smem row
#define ATILE (128 * ROWB)              // 18432 B
#define BTILE (256 * ROWB)              // 36864 B
#define HSTAGE (2 * ATILE + 2 * BTILE)  // 110592 B per stage
__global__ __launch_bounds__(256, 1) void head_gemm(
    const __nv_bfloat16* __restrict__ A0, const __nv_bfloat16* __restrict__ A1,
    const __nv_bfloat16* __restrict__ B0, const __nv_bfloat16* __restrict__ B1,
    float* __restrict__ C, const float* __restrict__ bias)
{
    if ((int)(blockIdx.y * 128) >= g_nk[0]) return;
    extern __shared__ char smem[];
    __shared__ int ridx[128];
    uint32_t sbase = smem_u32(smem);
    int tid = threadIdx.x, lane = tid & 31, wid = tid >> 5;
    int grp = lane >> 2, tig = lane & 3;
    int m_off = (wid >> 2) * 64;
    int n_off = (wid & 3) * 64;
    int col0 = blockIdx.x * 256;
    const int N = V;
    const __nv_bfloat16* Ap[2] = {A0, A1};
    const __nv_bfloat16* Bp[2] = {B0, B1};

    if (tid < 128) ridx[tid] = g_idx[blockIdx.y * 128 + tid];
    __syncthreads();

    float acc[4][8][4];
    #pragma unroll
    for (int i = 0; i < 4; i++)
        #pragma unroll
        for (int j = 0; j < 8; j++)
            #pragma unroll
            for (int k = 0; k < 4; k++) acc[i][j][k] = 0.f;

    auto load_stage = [&](int ch) {
        uint32_t sb = sbase + (ch & 1) * HSTAGE;
        int k0 = ch * 64;
        #pragma unroll
        for (int i = 0; i < 8; i++) {
            int idx = tid + i * 256;
            int r = idx >> 3, c8 = idx & 7;
            int limb = r >> 7, row = r & 127;
            uint32_t so = limb * ATILE + row * ROWB + c8 * 16;
            cp_async16(sb + so, Ap[limb] + (size_t)ridx[row] * 256 + k0 + c8 * 8);
        }
        #pragma unroll
        for (int i = 0; i < 16; i++) {
            int idx = tid + i * 256;
            int r = idx >> 3, c8 = idx & 7;
            int limb = r >> 8, row = r & 255;
            uint32_t so = 2 * ATILE + limb * BTILE + row * ROWB + c8 * 16;
            cp_async16(sb + so, Bp[limb] + (size_t)(col0 + row) * 256 + k0 + c8 * 8);
        }
    };

    load_stage(0); cp_commit();

    #pragma unroll
    for (int ch = 0; ch < 4; ch++) {
        if (ch + 1 < 4) { load_stage(ch + 1); cp_commit(); cp_wait<1>(); }
        else           { cp_wait<0>(); }
        __syncthreads();

        uint32_t sb = sbase + (ch & 1) * HSTAGE;
        #pragma unroll
        for (int ks = 0; ks < 4; ks++) {
            #pragma unroll
            for (int p = 0; p < 3; p++) {
                const int ta = (p == 2) ? 1 : 0;
                const int tb = (p == 1) ? 1 : 0;
                uint32_t a[4][4];
                #pragma unroll
                for (int mt = 0; mt < 4; mt++) {
                    uint32_t base = sb + ta * ATILE
                                  + (m_off + mt * 16 + grp) * ROWB + ks * 32 + tig * 4;
                    a[mt][0] = lds32(base);
                    a[mt][1] = lds32(base + 8 * ROWB);
                    a[mt][2] = lds32(base + 16);
                    a[mt][3] = lds32(base + 8 * ROWB + 16);
                }
                #pragma unroll
                for (int nt = 0; nt < 8; nt++) {
                    uint32_t base = sb + 2 * ATILE + tb * BTILE
                                  + (n_off + nt * 8 + grp) * ROWB + ks * 32 + tig * 4;
                    uint32_t b[2];
                    b[0] = lds32(base);
                    b[1] = lds32(base + 16);
                    #pragma unroll
                    for (int mt = 0; mt < 4; mt++)
                        mma16816(acc[mt][nt], a[mt], b);
                }
            }
        }
        __syncthreads();
    }

    int rl = m_off + grp;
    int cb = col0 + n_off + tig * 2;
    #pragma unroll
    for (int mt = 0; mt < 4; mt++) {
        int r0 = ridx[rl + mt * 16], r1 = ridx[rl + mt * 16 + 8];
        #pragma unroll
        for (int nt = 0; nt < 8; nt++) {
            int cc = cb + nt * 8;
            float b0 = bias[cc], b1 = bias[cc + 1];
            float2 v0 = make_float2(acc[mt][nt][0] + b0, acc[mt][nt][1] + b1);
            float2 v1 = make_float2(acc[mt][nt][2] + b0, acc[mt][nt][3] + b1);
            *(float2*)(C + (size_t)r0 * N + cc) = v0;
            *(float2*)(C + (size_t)r1 * N + cc) = v1;
        }
    }
}

// --------- fp32 SGEMM, gather/scatter rows (proven per-row math) ----------------
#define BM 128
#define BN 128
#define BK 16
#define TM 8
#define TN 8
__global__ __launch_bounds__(256) void sgemm_gs(const float* __restrict__ A,
                                               const float* __restrict__ B,
                                               float* __restrict__ C,
                                               int M, int N, int K) {
    if ((int)(blockIdx.y * BM) >= g_nk[0]) return;
    __shared__ float As[BK][BM];
    __shared__ float Bs[BK][BN];
    __shared__ int ridx[BM];
    int tid = threadIdx.x;
    int tx = tid & 15, ty = tid >> 4;
    int col0 = blockIdx.x * BN;
    if (tid < BM) ridx[tid] = g_idx[blockIdx.y * BM + tid];
    __syncthreads();
    float acc[TM][TN];
    #pragma unroll
    for (int i = 0; i < TM; i++)
        #pragma unroll
        for (int j = 0; j < TN; j++) acc[i][j] = 0.f;

    for (int k0 = 0; k0 < K; k0 += BK) {
        #pragma unroll
        for (int i = 0; i < 2; i++) {
            int idx = tid + i * 256;
            int r = idx >> 2;
            int c4 = (idx & 3) << 2;
            float4 va = *(const float4*)(A + (size_t)ridx[r] * K + k0 + c4);
            As[c4 + 0][r] = va.x; As[c4 + 1][r] = va.y;
            As[c4 + 2][r] = va.z; As[c4 + 3][r] = va.w;
            float4 vb = *(const float4*)(B + (size_t)(col0 + r) * K + k0 + c4);
            Bs[c4 + 0][r] = vb.x; Bs[c4 + 1][r] = vb.y;
            Bs[c4 + 2][r] = vb.z; Bs[c4 + 3][r] = vb.w;
        }
        __syncthreads();
        #pragma unroll
        for (int kk = 0; kk < BK; kk++) {
            float ra[TM], rb[TN];
            #pragma unroll
            for (int i = 0; i < TM; i++) ra[i] = As[kk][ty * TM + i];
            #pragma unroll
            for (int j = 0; j < TN; j++) rb[j] = Bs[kk][tx * TN + j];
            #pragma unroll
            for (int i = 0; i < TM; i++)
                #pragma unroll
                for (int j = 0; j < TN; j++)
                    acc[i][j] += ra[i] * rb[j];
        }
        __syncthreads();
    }
    #pragma unroll
    for (int i = 0; i < TM; i++) {
        int r = ridx[ty * TM + i];
        #pragma unroll
        for (int j = 0; j < TN; j += 4) {
            int c = col0 + tx * TN + j;
            float4 v = make_float4(acc[i][j], acc[i][j + 1], acc[i][j + 2], acc[i][j + 3]);
            *(float4*)(C + (size_t)r * N + c) = v;
        }
    }
}

// ---------------- head W limb split ----------------
__global__ void split2_kernel(const float* __restrict__ src,
                              __nv_bfloat16* __restrict__ h0,
                              __nv_bfloat16* __restrict__ h1, int n) {
    int i = blockIdx.x * 256 + threadIdx.x;
    if (i >= n) return;
    float v = src[i];
    __nv_bfloat16 a = __float2bfloat16(v);
    h0[i] = a;
    h1[i] = __float2bfloat16(v - __bfloat162float(a));
}

// ------- head fill row: out row for x==0 tokens = ln_b·W^T + head_b ----------
__global__ void fill_row_kernel(const float* __restrict__ ln_b,
                                const float* __restrict__ head_W,
                                const float* __restrict__ head_b) {
    int c = blockIdx.x * 256 + threadIdx.x;
    if (c >= V) return;
    float acc = 0.f;
    const float* w = head_W + (size_t)c * D;
    #pragma unroll 8
    for (int d = 0; d < D; d++) acc += ln_b[d] * w[d];
    g_fill[c] = acc + head_b[c];
}

// ---------------- fill dropped-token output rows ----------------
__global__ void bias_fill_kernel(float* __restrict__ out) {
    int s = blockIdx.x;
    if (g_keepf[s]) return;
    float* dst = out + (size_t)s * V;
    for (int c = threadIdx.x * 4; c < V; c += 1024) {
        float4 v = *(const float4*)(g_fill + c);
        *(float4*)(dst + c) = v;
    }
}

// -------- embedding gather fused with stats partials ----------------------------
// grid 32 x 256; block b: rows [b*128,(b+1)*128); thread t = dim t, serial rows.
__global__ void embed_stats_kernel(const int* __restrict__ tokens,
                                   const float* __restrict__ emb) {
    int b = blockIdx.x, t = threadIdx.x;
    float s = 0.f, s2 = 0.f;
    #pragma unroll 4
    for (int r = 0; r < 128; r++) {
        int tok = tokens[b * 128 + r];
        float v = emb[(size_t)tok * D + t];
        g_x[(size_t)(b * 128 + r) * D + t] = v;
        s += v; s2 += v * v;
    }
    g_psum[b][t] = s;
    g_psum2[b][t] = s2;
}

// -------- stats finalize: fixed-order 32-partial sum + mu/istd/absnb ------------
__global__ void stats_final_kernel(const float* __restrict__ buffers,
                                   const float* __restrict__ decays, int l) {
    int d = threadIdx.x;   // 256
    float s = 0.f, s2 = 0.f;
    #pragma unroll
    for (int b = 0; b < 32; b++) { s += g_psum[b][d]; s2 += g_psum2[b][d]; }
    float mu = s / (float)S;
    float var = (s2 - (float)S * mu * mu) / (float)(S - 1);
    g_mu[d] = mu;
    g_istd[d] = rsqrtf(var + 1e-6f);
    float dec = decays[l];
    float nb = dec * buffers[l * D + d] + (1.f - dec) * mu;
    g_absnb[d] = fabsf(nb);
}

// ---------------- apply AstroNorm + gate scores (warp-shuffle reduce) -----------
__global__ void norm_score_kernel(const float* __restrict__ gate_w, int l) {
    int s = blockIdx.x, d = threadIdx.x;
    float v = g_x[s * D + d];
    float mu = g_mu[d];
    float v2 = (fabsf(v - mu) > g_absnb[d] ? mu : v) * g_istd[d];
    g_x[s * D + d] = v2;
    float p = v2 * gate_w[l * D + d];
    #pragma unroll
    for (int off = 16; off > 0; off >>= 1)
        p += __shfl_down_sync(0xFFFFFFFFu, p, off);
    __shared__ float w[8];
    if ((d & 31) == 0) w[d >> 5] = p;
    __syncthreads();
    if (d == 0) {
        float t = 0.f;
        #pragma unroll
        for (int i = 0; i < 8; i++) t += w[i];
        g_scores[s] = t;
    }
}

// ---------------- k-th largest: parallel order statistic ----------------
__global__ void select_kernel() {
    __shared__ float sc[S];
    __shared__ int sgt[32][8], sge[32][8];
    int tid = threadIdx.x;
    for (int i = tid; i < S; i += 256) sc[i] = g_scores[i];
    __syncthreads();
    int c = tid >> 3, part = tid & 7;
    float v = sc[blockIdx.x * 32 + c];
    int gt = 0, ge = 0;
    int j0 = part * 512;
    #pragma unroll 8
    for (int j = j0; j < j0 + 512; j++) {
        float u = sc[j];
        gt += (u > v);
        ge += (u >= v);
    }
    sgt[c][part] = gt; sge[c][part] = ge;
    __syncthreads();
    if (part == 0) {
        int GT = 0, GE = 0;
        #pragma unroll
        for (int p = 0; p < 8; p++) { GT += sgt[c][p]; GE += sge[c][p]; }
        if (GT < KGATE && GE >= KGATE) g_thr[0] = v;
    }
}

// --------- stable partition: kept token indices first, then dropped -------------
__global__ void partition_kernel() {   // 1 block x 1024 threads
    __shared__ int sc[1024];
    __shared__ int s_nk;
    int tid = threadIdx.x;
    float thr = g_thr[0];
    int base = tid * 4;
    int f[4], cnt = 0;
    #pragma unroll
    for (int j = 0; j < 4; j++) {
        f[j] = (g_scores[base + j] > thr) ? 1 : 0;
        cnt += f[j];
    }
    sc[tid] = cnt;
    __syncthreads();
    for (int off = 1; off < 1024; off <<= 1) {
        int v = (tid >= off) ? sc[tid - off] : 0;
        __syncthreads();
        sc[tid] += v;
        __syncthreads();
    }
    if (tid == 1023) s_nk = sc[1023];
    __syncthreads();
    int nk = s_nk;
    int kb = sc[tid] - cnt;
    #pragma unroll
    for (int j = 0; j < 4; j++) {
        int s = base + j;
        if (f[j]) { g_idx[kb] = s; g_keepf[s] = 1; kb++; }
        else      { g_idx[nk + (s - kb)] = s; g_keepf[s] = 0; }
    }
    if (tid == 0) g_nk[0] = nk;
}

// ---------- routing mask (float4 reduce) ----------------
__global__ void gate_mask_kernel(const float* __restrict__ gating_W,
                                 const float* __restrict__ gating_b, int l) {
    int s = blockIdx.x, d = threadIdx.x;
    bool keep = g_scores[s] > g_thr[0];
    float v = keep ? g_x[s * D + d] : 0.f;

    __shared__ float4 sh4[256];
    const float* W = gating_W + l * E * D;
    sh4[d] = make_float4(v * W[d], v * W[D + d], v * W[2 * D + d], v * W[3 * D + d]);
    __syncthreads();
    for (int off = 128; off > 0; off >>= 1) {
        if (d < off) {
            float4 x = sh4[d], y = sh4[d + off];
            sh4[d] = make_float4(x.x + y.x, x.y + y.y, x.z + y.z, x.w + y.w);
        }
        __syncthreads();
    }
    if (d == 0) {
        float gs[E] = { sh4[0].x + gating_b[l * E + 0],
                        sh4[0].y + gating_b[l * E + 1],
                        sh4[0].z + gating_b[l * E + 2],
                        sh4[0].w + gating_b[l * E + 3] };
        float best = gs[0]; int excl = 0;
        #pragma unroll
        for (int e = 1; e < E; e++)
            if (gs[e] <= best) { best = gs[e]; excl = e; }
        #pragma unroll
        for (int e = 0; e < E; e++)
            g_mask[s * E + e] = (e == excl) ? 0.f : 1.f;
    }
}

// ------- combine expert outputs fused with next-layer stats partials ------------
// grid 32 x 256; block b: tokens [b*128,(b+1)*128) serial; thread o = output dim.
// Per-token x expression identical to prior combine (bit-exact x).
__global__ void combine_stats_kernel(const float* __restrict__ exp_b, int l) {
    int b = blockIdx.x, o = threadIdx.x;
    const float* eb = exp_b + l * E * D;
    float eb0 = eb[0 * D + o], eb1 = eb[1 * D + o], eb2 = eb[2 * D + o], eb3 = eb[3 * D + o];
    float s = 0.f, s2 = 0.f;
    for (int r = 0; r < 128; r++) {
        int tok = b * 128 + r;
        const float* m = g_mask + tok * E;
        float acc;
        if (g_keepf[tok]) {
            const float* y = g_y + (size_t)tok * (E * D) + o;
            acc  = m[0] * (y[0 * D] + eb0);
            acc += m[1] * (y[1 * D] + eb1);
            acc += m[2] * (y[2 * D] + eb2);
            acc += m[3] * (y[3 * D] + eb3);
        } else {
            acc  = m[0] * eb0;
            acc += m[1] * eb1;
            acc += m[2] * eb2;
            acc += m[3] * eb3;
        }
        g_x[(size_t)tok * D + o] = acc;
        s += acc; s2 += acc * acc;
    }
    g_psum[b][o] = s;
    g_psum2[b][o] = s2;
}

// ---------------- final LayerNorm + 2-limb split for head ----------------
__global__ void ln_kernel(const float* __restrict__ g, const float* __restrict__ b) {
    int s = blockIdx.x, d = threadIdx.x;
    float v = g_x[s * D + d];
    __shared__ float sh[256];
    sh[d] = v;
    __syncthreads();
    for (int off = 128; off > 0; off >>= 1) {
        if (d < off) sh[d] += sh[d + off];
        __syncthreads();
    }
    float mean = sh[0] / (float)D;
    __syncthreads();
    float c = v - mean;
    sh[d] = c * c;
    __syncthreads();
    for (int off = 128; off > 0; off >>= 1) {
        if (d < off) sh[d] += sh[d + off];
        __syncthreads();
    }
    float var = sh[0] / (float)D;
    float y = c * rsqrtf(var + 1e-5f) * g[d] + b[d];
    __nv_bfloat16 h = __float2bfloat16(y);
    g_xs0[s * D + d] = h;
    g_xs1[s * D + d] = __float2bfloat16(y - __bfloat162float(h));
}

// ---------------- launch ----------------
extern "C" void kernel_launch(void* const* d_in, const int* in_sizes, int n_in,
                              void* d_out, int out_size) {
    const int*   tokens   = (const int*)  d_in[0];
    const float* emb      = (const float*)d_in[1];
    const float* buffers  = (const float*)d_in[2];
    const float* decays   = (const float*)d_in[3];
    const float* gate_w   = (const float*)d_in[4];
    const float* gating_W = (const float*)d_in[5];
    const float* gating_b = (const float*)d_in[6];
    const float* exp_W    = (const float*)d_in[7];
    const float* exp_b    = (const float*)d_in[8];
    const float* ln_g     = (const float*)d_in[9];
    const float* ln_b     = (const float*)d_in[10];
    const float* head_W   = (const float*)d_in[11];
    const float* head_b   = (const float*)d_in[12];
    float* out = (float*)d_out;

    float *xp, *yp;
    cudaGetSymbolAddress((void**)&xp, g_x);
    cudaGetSymbolAddress((void**)&yp, g_y);
    __nv_bfloat16 *xs0, *xs1, *wh0, *wh1;
    cudaGetSymbolAddress((void**)&xs0, g_xs0);
    cudaGetSymbolAddress((void**)&xs1, g_xs1);
    cudaGetSymbolAddress((void**)&wh0, g_wh0);
    cudaGetSymbolAddress((void**)&wh1, g_wh1);

    const int SMEMH = 2 * HSTAGE;   // 221184
    cudaFuncSetAttribute(head_gemm, cudaFuncAttributeMaxDynamicSharedMemorySize, SMEMH);

    split2_kernel<<<(V * D + 255) / 256, 256>>>(head_W, wh0, wh1, V * D);
    fill_row_kernel<<<(V + 255) / 256, 256>>>(ln_b, head_W, head_b);

    embed_stats_kernel<<<32, 256>>>(tokens, emb);

    for (int l = 0; l < L; l++) {
        stats_final_kernel<<<1, 256>>>(buffers, decays, l);
        norm_score_kernel<<<S, 256>>>(gate_w, l);
        select_kernel<<<128, 256>>>();
        partition_kernel<<<1, 1024>>>();
        gate_mask_kernel<<<S, 256>>>(gating_W, gating_b, l);
        dim3 ge((E * D) / BN, S / BM);   // (8, 32); tiles past NK early-exit
        sgemm_gs<<<ge, 256>>>(xp, exp_W + (size_t)l * E * D * D, yp, S, E * D, D);
        combine_stats_kernel<<<32, 256>>>(exp_b, l);   // x + next-layer partials
    }

    ln_kernel<<<S, 256>>>(ln_g, ln_b);

    dim3 gh(V / 256, S / 128);           // (125, 32); tiles past NK4 early-exit
    head_gemm<<<gh, 256, SMEMH>>>(xs0, xs1, wh0, wh1, out, head_b);
    bias_fill_kernel<<<S, 256>>>(out);
}

// round 13
// speedup vs baseline: 1.2118x; 1.2118x over previous
#include <cuda_runtime.h>
#include <cuda_bf16.h>
#include <cstdint>

#define S 4096
#define D 256
#define L 4
#define E 4
#define V 32000
#define KGATE 2201   // int(4096 * sigmoid(0.15))

// ---------------- device scratch (no allocations allowed) ----------------
__device__ float g_x[S * D];            // fp32 activations
__device__ float g_y[S * E * D];        // all-expert outputs
__device__ float g_scores[S];
__device__ float g_mu[D];
__device__ float g_istd[D];
__device__ float g_absnb[D];
__device__ float g_thr[1];
__device__ float g_mask[S * E];
__device__ int   g_idx[S];              // permutation: kept rows first
__device__ int   g_keepf[S];            // keep flag per token
__device__ int   g_nk[1];               // number of kept tokens
__device__ float g_fill[V];             // head output row for dropped tokens
__device__ __nv_bfloat16 g_xs0[S * D], g_xs1[S * D];   // LN'd x limbs (head A)
__device__ __nv_bfloat16 g_wh0[V * D], g_wh1[V * D];   // head W limbs

// ================= PTX helpers (sm_80-class, legal on plain sm_103) ==========
__device__ __forceinline__ uint32_t smem_u32(const void* p) {
    uint32_t a;
    asm("{ .reg .u64 t; cvta.to.shared.u64 t, %1; cvt.u32.u64 %0, t; }" : "=r"(a) : "l"(p));
    return a;
}
__device__ __forceinline__ void cp_async16(uint32_t s, const void* g) {
    asm volatile("cp.async.cg.shared.global [%0], [%1], 16;" :: "r"(s), "l"(g));
}
__device__ __forceinline__ void cp_commit() {
    asm volatile("cp.async.commit_group;");
}
template <int N>
__device__ __forceinline__ void cp_wait() {
    asm volatile("cp.async.wait_group %0;" :: "n"(N));
}
__device__ __forceinline__ uint32_t lds32(uint32_t addr) {
    uint32_t v;
    asm volatile("ld.shared.b32 %0, [%1];" : "=r"(v) : "r"(addr));
    return v;
}
__device__ __forceinline__ void mma16816(float* c, const uint32_t* a, const uint32_t* b) {
    asm volatile("mma.sync.aligned.m16n8k16.row.col.f32.bf16.bf16.f32 "
                 "{%0,%1,%2,%3}, {%4,%5,%6,%7}, {%8,%9}, {%0,%1,%2,%3};"
                 : "+f"(c[0]), "+f"(c[1]), "+f"(c[2]), "+f"(c[3])
                 : "r"(a[0]), "r"(a[1]), "r"(a[2]), "r"(a[3]), "r"(b[0]), "r"(b[1]));
}

// =============== head GEMM (proven R9: lds32 frags; row gather/scatter) =========
#define ROWB 144                        // 64 bf16 + pad = 144 B per smem row
#define ATILE (128 * ROWB)              // 18432 B
#define BTILE (256 * ROWB)              // 36864 B
#define HSTAGE (2 * ATILE + 2 * BTILE)  // 110592 B per stage
__global__ __launch_bounds__(256, 1) void head_gemm(
    const __nv_bfloat16* __restrict__ A0, const __nv_bfloat16* __restrict__ A1,
    const __nv_bfloat16* __restrict__ B0, const __nv_bfloat16* __restrict__ B1,
    float* __restrict__ C, const float* __restrict__ bias)
{
    if ((int)(blockIdx.y * 128) >= g_nk[0]) return;
    extern __shared__ char smem[];
    __shared__ int ridx[128];
    uint32_t sbase = smem_u32(smem);
    int tid = threadIdx.x, lane = tid & 31, wid = tid >> 5;
    int grp = lane >> 2, tig = lane & 3;
    int m_off = (wid >> 2) * 64;
    int n_off = (wid & 3) * 64;
    int col0 = blockIdx.x * 256;
    const int N = V;
    const __nv_bfloat16* Ap[2] = {A0, A1};
    const __nv_bfloat16* Bp[2] = {B0, B1};

    if (tid < 128) ridx[tid] = g_idx[blockIdx.y * 128 + tid];
    __syncthreads();

    float acc[4][8][4];
    #pragma unroll
    for (int i = 0; i < 4; i++)
        #pragma unroll
        for (int j = 0; j < 8; j++)
            #pragma unroll
            for (int k = 0; k < 4; k++) acc[i][j][k] = 0.f;

    auto load_stage = [&](int ch) {
        uint32_t sb = sbase + (ch & 1) * HSTAGE;
        int k0 = ch * 64;
        #pragma unroll
        for (int i = 0; i < 8; i++) {
            int idx = tid + i * 256;
            int r = idx >> 3, c8 = idx & 7;
            int limb = r >> 7, row = r & 127;
            uint32_t so = limb * ATILE + row * ROWB + c8 * 16;
            cp_async16(sb + so, Ap[limb] + (size_t)ridx[row] * 256 + k0 + c8 * 8);
        }
        #pragma unroll
        for (int i = 0; i < 16; i++) {
            int idx = tid + i * 256;
            int r = idx >> 3, c8 = idx & 7;
            int limb = r >> 8, row = r & 255;
            uint32_t so = 2 * ATILE + limb * BTILE + row * ROWB + c8 * 16;
            cp_async16(sb + so, Bp[limb] + (size_t)(col0 + row) * 256 + k0 + c8 * 8);
        }
    };

    load_stage(0); cp_commit();

    #pragma unroll
    for (int ch = 0; ch < 4; ch++) {
        if (ch + 1 < 4) { load_stage(ch + 1); cp_commit(); cp_wait<1>(); }
        else           { cp_wait<0>(); }
        __syncthreads();

        uint32_t sb = sbase + (ch & 1) * HSTAGE;
        #pragma unroll
        for (int ks = 0; ks < 4; ks++) {
            #pragma unroll
            for (int p = 0; p < 3; p++) {
                const int ta = (p == 2) ? 1 : 0;
                const int tb = (p == 1) ? 1 : 0;
                uint32_t a[4][4];
                #pragma unroll
                for (int mt = 0; mt < 4; mt++) {
                    uint32_t base = sb + ta * ATILE
                                  + (m_off + mt * 16 + grp) * ROWB + ks * 32 + tig * 4;
                    a[mt][0] = lds32(base);
                    a[mt][1] = lds32(base + 8 * ROWB);
                    a[mt][2] = lds32(base + 16);
                    a[mt][3] = lds32(base + 8 * ROWB + 16);
                }
                #pragma unroll
                for (int nt = 0; nt < 8; nt++) {
                    uint32_t base = sb + 2 * ATILE + tb * BTILE
                                  + (n_off + nt * 8 + grp) * ROWB + ks * 32 + tig * 4;
                    uint32_t b[2];
                    b[0] = lds32(base);
                    b[1] = lds32(base + 16);
                    #pragma unroll
                    for (int mt = 0; mt < 4; mt++)
                        mma16816(acc[mt][nt], a[mt], b);
                }
            }
        }
        __syncthreads();
    }

    int rl = m_off + grp;
    int cb = col0 + n_off + tig * 2;
    #pragma unroll
    for (int mt = 0; mt < 4; mt++) {
        int r0 = ridx[rl + mt * 16], r1 = ridx[rl + mt * 16 + 8];
        #pragma unroll
        for (int nt = 0; nt < 8; nt++) {
            int cc = cb + nt * 8;
            float b0 = bias[cc], b1 = bias[cc + 1];
            float2 v0 = make_float2(acc[mt][nt][0] + b0, acc[mt][nt][1] + b1);
            float2 v1 = make_float2(acc[mt][nt][2] + b0, acc[mt][nt][3] + b1);
            *(float2*)(C + (size_t)r0 * N + cc) = v0;
            *(float2*)(C + (size_t)r1 * N + cc) = v1;
        }
    }
}

// --------- fp32 SGEMM, gather/scatter rows (proven per-row math) ----------------
#define BM 128
#define BN 128
#define BK 16
#define TM 8
#define TN 8
__global__ __launch_bounds__(256) void sgemm_gs(const float* __restrict__ A,
                                               const float* __restrict__ B,
                                               float* __restrict__ C,
                                               int M, int N, int K) {
    if ((int)(blockIdx.y * BM) >= g_nk[0]) return;
    __shared__ float As[BK][BM];
    __shared__ float Bs[BK][BN];
    __shared__ int ridx[BM];
    int tid = threadIdx.x;
    int tx = tid & 15, ty = tid >> 4;
    int col0 = blockIdx.x * BN;
    if (tid < BM) ridx[tid] = g_idx[blockIdx.y * BM + tid];
    __syncthreads();
    float acc[TM][TN];
    #pragma unroll
    for (int i = 0; i < TM; i++)
        #pragma unroll
        for (int j = 0; j < TN; j++) acc[i][j] = 0.f;

    for (int k0 = 0; k0 < K; k0 += BK) {
        #pragma unroll
        for (int i = 0; i < 2; i++) {
            int idx = tid + i * 256;
            int r = idx >> 2;
            int c4 = (idx & 3) << 2;
            float4 va = *(const float4*)(A + (size_t)ridx[r] * K + k0 + c4);
            As[c4 + 0][r] = va.x; As[c4 + 1][r] = va.y;
            As[c4 + 2][r] = va.z; As[c4 + 3][r] = va.w;
            float4 vb = *(const float4*)(B + (size_t)(col0 + r) * K + k0 + c4);
            Bs[c4 + 0][r] = vb.x; Bs[c4 + 1][r] = vb.y;
            Bs[c4 + 2][r] = vb.z; Bs[c4 + 3][r] = vb.w;
        }
        __syncthreads();
        #pragma unroll
        for (int kk = 0; kk < BK; kk++) {
            float ra[TM], rb[TN];
            #pragma unroll
            for (int i = 0; i < TM; i++) ra[i] = As[kk][ty * TM + i];
            #pragma unroll
            for (int j = 0; j < TN; j++) rb[j] = Bs[kk][tx * TN + j];
            #pragma unroll
            for (int i = 0; i < TM; i++)
                #pragma unroll
                for (int j = 0; j < TN; j++)
                    acc[i][j] += ra[i] * rb[j];
        }
        __syncthreads();
    }
    #pragma unroll
    for (int i = 0; i < TM; i++) {
        int r = ridx[ty * TM + i];
        #pragma unroll
        for (int j = 0; j < TN; j += 4) {
            int c = col0 + tx * TN + j;
            float4 v = make_float4(acc[i][j], acc[i][j + 1], acc[i][j + 2], acc[i][j + 3]);
            *(float4*)(C + (size_t)r * N + c) = v;
        }
    }
}

// ---------------- head W limb split ----------------
__global__ void split2_kernel(const float* __restrict__ src,
                              __nv_bfloat16* __restrict__ h0,
                              __nv_bfloat16* __restrict__ h1, int n) {
    int i = blockIdx.x * 256 + threadIdx.x;
    if (i >= n) return;
    float v = src[i];
    __nv_bfloat16 a = __float2bfloat16(v);
    h0[i] = a;
    h1[i] = __float2bfloat16(v - __bfloat162float(a));
}

// ------- head fill row (coalesced warp-per-column): g_fill = ln_b·W^T + head_b --
// grid 4000 x 256: 8 warps/block, 1 column per warp. Lanes read head_W row
// coalesced (lane + k*32), shuffle-reduce. Output feeds ONLY dropped rows of the
// final output (no gate feedback) so the new summation order is cliff-safe.
__global__ void fill_row_kernel(const float* __restrict__ ln_b,
                                const float* __restrict__ head_W,
                                const float* __restrict__ head_b) {
    __shared__ float lb[D];
    int tid = threadIdx.x;
    if (tid < D) lb[tid] = ln_b[tid];
    __syncthreads();
    int lane = tid & 31, w = tid >> 5;
    int c = blockIdx.x * 8 + w;
    if (c >= V) return;
    const float* wr = head_W + (size_t)c * D;
    float s = 0.f;
    #pragma unroll
    for (int k = 0; k < 8; k++) {
        int d = k * 32 + lane;
        s += lb[d] * wr[d];
    }
    #pragma unroll
    for (int off = 16; off > 0; off >>= 1)
        s += __shfl_down_sync(0xFFFFFFFFu, s, off);
    if (lane == 0) g_fill[c] = s + head_b[c];
}

// ---------------- fill dropped-token output rows ----------------
__global__ void bias_fill_kernel(float* __restrict__ out) {
    int s = blockIdx.x;
    if (g_keepf[s]) return;
    float* dst = out + (size_t)s * V;
    for (int c = threadIdx.x * 4; c < V; c += 1024) {
        float4 v = *(const float4*)(g_fill + c);
        *(float4*)(dst + c) = v;
    }
}

// ---------------- embedding gather ----------------
__global__ void embed_kernel(const int* __restrict__ tokens,
                             const float* __restrict__ emb) {
    int s = blockIdx.x, d = threadIdx.x;
    g_x[s * D + d] = emb[(size_t)tokens[s] * D + d];
}

// ---------------- AstroNorm column stats (R9-exact order) ----------------
__global__ void stats_kernel(const float* __restrict__ buffers,
                             const float* __restrict__ decays, int l) {
    int d = blockIdx.x, tid = threadIdx.x;
    float s = 0.f, s2 = 0.f;
    for (int i = tid; i < S; i += 256) {
        float v = g_x[i * D + d];
        s += v; s2 += v * v;
    }
    __shared__ float sh[256], sh2[256];
    sh[tid] = s; sh2[tid] = s2;
    __syncthreads();
    for (int off = 128; off > 0; off >>= 1) {
        if (tid < off) { sh[tid] += sh[tid + off]; sh2[tid] += sh2[tid + off]; }
        __syncthreads();
    }
    if (tid == 0) {
        float mu = sh[0] / (float)S;
        float var = (sh2[0] - (float)S * mu * mu) / (float)(S - 1);
        g_mu[d] = mu;
        g_istd[d] = rsqrtf(var + 1e-6f);
        float dec = decays[l];
        float nb = dec * buffers[l * D + d] + (1.f - dec) * mu;
        g_absnb[d] = fabsf(nb);
    }
}

// ---------------- apply AstroNorm + gate scores (R9-exact order) ----------------
__global__ void norm_score_kernel(const float* __restrict__ gate_w, int l) {
    int s = blockIdx.x, d = threadIdx.x;
    float v = g_x[s * D + d];
    float mu = g_mu[d];
    float v2 = (fabsf(v - mu) > g_absnb[d] ? mu : v) * g_istd[d];
    g_x[s * D + d] = v2;
    float p = v2 * gate_w[l * D + d];
    #pragma unroll
    for (int off = 16; off > 0; off >>= 1)
        p += __shfl_down_sync(0xFFFFFFFFu, p, off);
    __shared__ float w[8];
    if ((d & 31) == 0) w[d >> 5] = p;
    __syncthreads();
    if (d == 0) {
        float t = 0.f;
        #pragma unroll
        for (int i = 0; i < 8; i++) t += w[i];
        g_scores[s] = t;
    }
}

// ---------------- k-th largest: parallel order statistic ----------------
__global__ void select_kernel() {
    __shared__ float sc[S];
    __shared__ int sgt[32][8], sge[32][8];
    int tid = threadIdx.x;
    for (int i = tid; i < S; i += 256) sc[i] = g_scores[i];
    __syncthreads();
    int c = tid >> 3, part = tid & 7;
    float v = sc[blockIdx.x * 32 + c];
    int gt = 0, ge = 0;
    int j0 = part * 512;
    #pragma unroll 8
    for (int j = j0; j < j0 + 512; j++) {
        float u = sc[j];
        gt += (u > v);
        ge += (u >= v);
    }
    sgt[c][part] = gt; sge[c][part] = ge;
    __syncthreads();
    if (part == 0) {
        int GT = 0, GE = 0;
        #pragma unroll
        for (int p = 0; p < 8; p++) { GT += sgt[c][p]; GE += sge[c][p]; }
        if (GT < KGATE && GE >= KGATE) g_thr[0] = v;
    }
}

// --------- stable partition: kept token indices first, then dropped -------------
__global__ void partition_kernel() {   // 1 block x 1024 threads
    __shared__ int sc[1024];
    __shared__ int s_nk;
    int tid = threadIdx.x;
    float thr = g_thr[0];
    int base = tid * 4;
    int f[4], cnt = 0;
    #pragma unroll
    for (int j = 0; j < 4; j++) {
        f[j] = (g_scores[base + j] > thr) ? 1 : 0;
        cnt += f[j];
    }
    sc[tid] = cnt;
    __syncthreads();
    for (int off = 1; off < 1024; off <<= 1) {
        int v = (tid >= off) ? sc[tid - off] : 0;
        __syncthreads();
        sc[tid] += v;
        __syncthreads();
    }
    if (tid == 1023) s_nk = sc[1023];
    __syncthreads();
    int nk = s_nk;
    int kb = sc[tid] - cnt;
    #pragma unroll
    for (int j = 0; j < 4; j++) {
        int s = base + j;
        if (f[j]) { g_idx[kb] = s; g_keepf[s] = 1; kb++; }
        else      { g_idx[nk + (s - kb)] = s; g_keepf[s] = 0; }
    }
    if (tid == 0) g_nk[0] = nk;
}

// ---------- routing mask (float4 reduce, R9-exact) ----------------
__global__ void gate_mask_kernel(const float* __restrict__ gating_W,
                                 const float* __restrict__ gating_b, int l) {
    int s = blockIdx.x, d = threadIdx.x;
    bool keep = g_scores[s] > g_thr[0];
    float v = keep ? g_x[s * D + d] : 0.f;

    __shared__ float4 sh4[256];
    const float* W = gating_W + l * E * D;
    sh4[d] = make_float4(v * W[d], v * W[D + d], v * W[2 * D + d], v * W[3 * D + d]);
    __syncthreads();
    for (int off = 128; off > 0; off >>= 1) {
        if (d < off) {
            float4 x = sh4[d], y = sh4[d + off];
            sh4[d] = make_float4(x.x + y.x, x.y + y.y, x.z + y.z, x.w + y.w);
        }
        __syncthreads();
    }
    if (d == 0) {
        float gs[E] = { sh4[0].x + gating_b[l * E + 0],
                        sh4[0].y + gating_b[l * E + 1],
                        sh4[0].z + gating_b[l * E + 2],
                        sh4[0].w + gating_b[l * E + 3] };
        float best = gs[0]; int excl = 0;
        #pragma unroll
        for (int e = 1; e < E; e++)
            if (gs[e] <= best) { best = gs[e]; excl = e; }
        #pragma unroll
        for (int e = 0; e < E; e++)
            g_mask[s * E + e] = (e == excl) ? 0.f : 1.f;
    }
}

// ---------------- combine expert outputs with mask (R9-exact) ----------------
__global__ void combine_kernel(const float* __restrict__ exp_b, int l) {
    int s = blockIdx.x, o = threadIdx.x;
    float acc = 0.f;
    if (g_keepf[s]) {
        #pragma unroll
        for (int e = 0; e < E; e++) {
            float m = g_mask[s * E + e];
            acc += m * (g_y[(size_t)s * (E * D) + e * D + o] + exp_b[l * E * D + e * D + o]);
        }
    } else {
        #pragma unroll
        for (int e = 0; e < E; e++)
            acc += g_mask[s * E + e] * exp_b[l * E * D + e * D + o];
    }
    g_x[s * D + o] = acc;
}

// ---------------- final LayerNorm + 2-limb split for head ----------------
__global__ void ln_kernel(const float* __restrict__ g, const float* __restrict__ b) {
    int s = blockIdx.x, d = threadIdx.x;
    float v = g_x[s * D + d];
    __shared__ float sh[256];
    sh[d] = v;
    __syncthreads();
    for (int off = 128; off > 0; off >>= 1) {
        if (d < off) sh[d] += sh[d + off];
        __syncthreads();
    }
    float mean = sh[0] / (float)D;
    __syncthreads();
    float c = v - mean;
    sh[d] = c * c;
    __syncthreads();
    for (int off = 128; off > 0; off >>= 1) {
        if (d < off) sh[d] += sh[d + off];
        __syncthreads();
    }
    float var = sh[0] / (float)D;
    float y = c * rsqrtf(var + 1e-5f) * g[d] + b[d];
    __nv_bfloat16 h = __float2bfloat16(y);
    g_xs0[s * D + d] = h;
    g_xs1[s * D + d] = __float2bfloat16(y - __bfloat162float(h));
}

// ---------------- launch ----------------
extern "C" void kernel_launch(void* const* d_in, const int* in_sizes, int n_in,
                              void* d_out, int out_size) {
    const int*   tokens   = (const int*)  d_in[0];
    const float* emb      = (const float*)d_in[1];
    const float* buffers  = (const float*)d_in[2];
    const float* decays   = (const float*)d_in[3];
    const float* gate_w   = (const float*)d_in[4];
    const float* gating_W = (const float*)d_in[5];
    const float* gating_b = (const float*)d_in[6];
    const float* exp_W    = (const float*)d_in[7];
    const float* exp_b    = (const float*)d_in[8];
    const float* ln_g     = (const float*)d_in[9];
    const float* ln_b     = (const float*)d_in[10];
    const float* head_W   = (const float*)d_in[11];
    const float* head_b   = (const float*)d_in[12];
    float* out = (float*)d_out;

    float *xp, *yp;
    cudaGetSymbolAddress((void**)&xp, g_x);
    cudaGetSymbolAddress((void**)&yp, g_y);
    __nv_bfloat16 *xs0, *xs1, *wh0, *wh1;
    cudaGetSymbolAddress((void**)&xs0, g_xs0);
    cudaGetSymbolAddress((void**)&xs1, g_xs1);
    cudaGetSymbolAddress((void**)&wh0, g_wh0);
    cudaGetSymbolAddress((void**)&wh1, g_wh1);

    const int SMEMH = 2 * HSTAGE;   // 221184
    cudaFuncSetAttribute(head_gemm, cudaFuncAttributeMaxDynamicSharedMemorySize, SMEMH);

    split2_kernel<<<(V * D + 255) / 256, 256>>>(head_W, wh0, wh1, V * D);
    fill_row_kernel<<<V / 8, 256>>>(ln_b, head_W, head_b);

    embed_kernel<<<S, 256>>>(tokens, emb);

    for (int l = 0; l < L; l++) {
        stats_kernel<<<D, 256>>>(buffers, decays, l);
        norm_score_kernel<<<S, 256>>>(gate_w, l);
        select_kernel<<<128, 256>>>();
        partition_kernel<<<1, 1024>>>();
        gate_mask_kernel<<<S, 256>>>(gating_W, gating_b, l);
        dim3 ge((E * D) / BN, S / BM);   // (8, 32); tiles past NK early-exit
        sgemm_gs<<<ge, 256>>>(xp, exp_W + (size_t)l * E * D * D, yp, S, E * D, D);
        combine_kernel<<<S, 256>>>(exp_b, l);
    }

    ln_kernel<<<S, 256>>>(ln_g, ln_b);

    dim3 gh(V / 256, S / 128);           // (125, 32); tiles past NK4 early-exit
    head_gemm<<<gh, 256, SMEMH>>>(xs0, xs1, wh0, wh1, out, head_b);
    bias_fill_kernel<<<S, 256>>>(out);
}

// round 14
// speedup vs baseline: 1.2868x; 1.0619x over previous
#include <cuda_runtime.h>
#include <cuda_bf16.h>
#include <cstdint>

#define S 4096
#define D 256
#define L 4
#define E 4
#define V 32000
#define KGATE 2201   // int(4096 * sigmoid(0.15))

// ---------------- device scratch (no allocations allowed) ----------------
__device__ float g_x[S * D];            // fp32 activations
__device__ float g_y[S * E * D];        // all-expert outputs
__device__ float g_scores[S];
__device__ float g_mu[D];
__device__ float g_istd[D];
__device__ float g_absnb[D];
__device__ float g_thr[1];
__device__ float g_mask[S * E];
__device__ int   g_idx[S];              // permutation: kept rows first
__device__ int   g_keepf[S];            // keep flag per token
__device__ int   g_nk[1];               // number of kept tokens
__device__ float g_fill[V];             // head output row for dropped tokens
__device__ __nv_bfloat16 g_xs0[S * D], g_xs1[S * D];   // LN'd x limbs (head A)
__device__ __nv_bfloat16 g_wh0[V * D], g_wh1[V * D];   // head W limbs

// ================= PTX helpers (sm_80-class, legal on plain sm_103) ==========
__device__ __forceinline__ uint32_t smem_u32(const void* p) {
    uint32_t a;
    asm("{ .reg .u64 t; cvta.to.shared.u64 t, %1; cvt.u32.u64 %0, t; }" : "=r"(a) : "l"(p));
    return a;
}
__device__ __forceinline__ void cp_async16(uint32_t s, const void* g) {
    asm volatile("cp.async.cg.shared.global [%0], [%1], 16;" :: "r"(s), "l"(g));
}
__device__ __forceinline__ void cp_commit() {
    asm volatile("cp.async.commit_group;");
}
template <int N>
__device__ __forceinline__ void cp_wait() {
    asm volatile("cp.async.wait_group %0;" :: "n"(N));
}
__device__ __forceinline__ void ldsm_x4(uint32_t& r0, uint32_t& r1, uint32_t& r2, uint32_t& r3,
                                        uint32_t addr) {
    asm volatile("ldmatrix.sync.aligned.m8n8.x4.shared.b16 {%0,%1,%2,%3}, [%4];"
                 : "=r"(r0), "=r"(r1), "=r"(r2), "=r"(r3) : "r"(addr));
}
__device__ __forceinline__ void mma16816(float* c, const uint32_t* a, const uint32_t* b) {
    asm volatile("mma.sync.aligned.m16n8k16.row.col.f32.bf16.bf16.f32 "
                 "{%0,%1,%2,%3}, {%4,%5,%6,%7}, {%8,%9}, {%0,%1,%2,%3};"
                 : "+f"(c[0]), "+f"(c[1]), "+f"(c[2]), "+f"(c[3])
                 : "r"(a[0]), "r"(a[1]), "r"(a[2]), "r"(a[3]), "r"(b[0]), "r"(b[1]));
}

// ===== head GEMM (R10 ldmatrix version — passed R10; mapping bit-proven R3==R4) ==
#define ROWB 144                        // 64 bf16 + pad = 144 B per smem row
#define ATILE (128 * ROWB)              // 18432 B
#define BTILE (256 * ROWB)              // 36864 B
#define HSTAGE (2 * ATILE + 2 * BTILE)  // 110592 B per stage
__global__ __launch_bounds__(256, 1) void head_gemm(
    const __nv_bfloat16* __restrict__ A0, const __nv_bfloat16* __restrict__ A1,
    const __nv_bfloat16* __restrict__ B0, const __nv_bfloat16* __restrict__ B1,
    float* __restrict__ C, const float* __restrict__ bias)
{
    if ((int)(blockIdx.y * 128) >= g_nk[0]) return;
    extern __shared__ char smem[];
    __shared__ int ridx[128];
    uint32_t sbase = smem_u32(smem);
    int tid = threadIdx.x, lane = tid & 31, wid = tid >> 5;
    int grp = lane >> 2, tig = lane & 3;
    int m_off = (wid >> 2) * 64;
    int n_off = (wid & 3) * 64;
    int col0 = blockIdx.x * 256;
    const int N = V;
    const __nv_bfloat16* Ap[2] = {A0, A1};
    const __nv_bfloat16* Bp[2] = {B0, B1};

    if (tid < 128) ridx[tid] = g_idx[blockIdx.y * 128 + tid];
    __syncthreads();

    float acc[4][8][4];
    #pragma unroll
    for (int i = 0; i < 4; i++)
        #pragma unroll
        for (int j = 0; j < 8; j++)
            #pragma unroll
            for (int k = 0; k < 4; k++) acc[i][j][k] = 0.f;

    auto load_stage = [&](int ch) {
        uint32_t sb = sbase + (ch & 1) * HSTAGE;
        int k0 = ch * 64;
        #pragma unroll
        for (int i = 0; i < 8; i++) {
            int idx = tid + i * 256;
            int r = idx >> 3, c8 = idx & 7;
            int limb = r >> 7, row = r & 127;
            uint32_t so = limb * ATILE + row * ROWB + c8 * 16;
            cp_async16(sb + so, Ap[limb] + (size_t)ridx[row] * 256 + k0 + c8 * 8);
        }
        #pragma unroll
        for (int i = 0; i < 16; i++) {
            int idx = tid + i * 256;
            int r = idx >> 3, c8 = idx & 7;
            int limb = r >> 8, row = r & 255;
            uint32_t so = 2 * ATILE + limb * BTILE + row * ROWB + c8 * 16;
            cp_async16(sb + so, Bp[limb] + (size_t)(col0 + row) * 256 + k0 + c8 * 8);
        }
    };

    load_stage(0); cp_commit();

    #pragma unroll
    for (int ch = 0; ch < 4; ch++) {
        if (ch + 1 < 4) { load_stage(ch + 1); cp_commit(); cp_wait<1>(); }
        else           { cp_wait<0>(); }
        __syncthreads();

        uint32_t sb = sbase + (ch & 1) * HSTAGE;
        #pragma unroll
        for (int ks = 0; ks < 4; ks++) {
            #pragma unroll
            for (int p = 0; p < 3; p++) {
                const int ta = (p == 2) ? 1 : 0;
                const int tb = (p == 1) ? 1 : 0;
                uint32_t a[4][4];
                #pragma unroll
                for (int mt = 0; mt < 4; mt++) {
                    uint32_t ad = sb + ta * ATILE
                                + (m_off + mt * 16 + (lane & 15)) * ROWB
                                + ks * 32 + (lane >> 4) * 16;
                    ldsm_x4(a[mt][0], a[mt][1], a[mt][2], a[mt][3], ad);
                }
                uint32_t b[8][2];
                #pragma unroll
                for (int nh = 0; nh < 4; nh++) {
                    int g2 = lane >> 3;
                    int brow = n_off + nh * 16 + (lane & 7) + (g2 >> 1) * 8;
                    uint32_t bd = sb + 2 * ATILE + tb * BTILE
                                + brow * ROWB + ks * 32 + (g2 & 1) * 16;
                    uint32_t r0, r1, r2, r3;
                    ldsm_x4(r0, r1, r2, r3, bd);
                    b[nh * 2][0] = r0;     b[nh * 2][1] = r1;
                    b[nh * 2 + 1][0] = r2; b[nh * 2 + 1][1] = r3;
                }
                #pragma unroll
                for (int mt = 0; mt < 4; mt++)
                    #pragma unroll
                    for (int nt = 0; nt < 8; nt++)
                        mma16816(acc[mt][nt], a[mt], b[nt]);
            }
        }
        __syncthreads();
    }

    int rl = m_off + grp;
    int cb = col0 + n_off + tig * 2;
    #pragma unroll
    for (int mt = 0; mt < 4; mt++) {
        int r0 = ridx[rl + mt * 16], r1 = ridx[rl + mt * 16 + 8];
        #pragma unroll
        for (int nt = 0; nt < 8; nt++) {
            int cc = cb + nt * 8;
            float b0 = bias[cc], b1 = bias[cc + 1];
            float2 v0 = make_float2(acc[mt][nt][0] + b0, acc[mt][nt][1] + b1);
            float2 v1 = make_float2(acc[mt][nt][2] + b0, acc[mt][nt][3] + b1);
            *(float2*)(C + (size_t)r0 * N + cc) = v0;
            *(float2*)(C + (size_t)r1 * N + cc) = v1;
        }
    }
}

// --------- fp32 SGEMM, gather/scatter rows (proven per-row math) ----------------
#define BM 128
#define BN 128
#define BK 16
#define TM 8
#define TN 8
__global__ __launch_bounds__(256) void sgemm_gs(const float* __restrict__ A,
                                               const float* __restrict__ B,
                                               float* __restrict__ C,
                                               int M, int N, int K) {
    if ((int)(blockIdx.y * BM) >= g_nk[0]) return;
    __shared__ float As[BK][BM];
    __shared__ float Bs[BK][BN];
    __shared__ int ridx[BM];
    int tid = threadIdx.x;
    int tx = tid & 15, ty = tid >> 4;
    int col0 = blockIdx.x * BN;
    if (tid < BM) ridx[tid] = g_idx[blockIdx.y * BM + tid];
    __syncthreads();
    float acc[TM][TN];
    #pragma unroll
    for (int i = 0; i < TM; i++)
        #pragma unroll
        for (int j = 0; j < TN; j++) acc[i][j] = 0.f;

    for (int k0 = 0; k0 < K; k0 += BK) {
        #pragma unroll
        for (int i = 0; i < 2; i++) {
            int idx = tid + i * 256;
            int r = idx >> 2;
            int c4 = (idx & 3) << 2;
            float4 va = *(const float4*)(A + (size_t)ridx[r] * K + k0 + c4);
            As[c4 + 0][r] = va.x; As[c4 + 1][r] = va.y;
            As[c4 + 2][r] = va.z; As[c4 + 3][r] = va.w;
            float4 vb = *(const float4*)(B + (size_t)(col0 + r) * K + k0 + c4);
            Bs[c4 + 0][r] = vb.x; Bs[c4 + 1][r] = vb.y;
            Bs[c4 + 2][r] = vb.z; Bs[c4 + 3][r] = vb.w;
        }
        __syncthreads();
        #pragma unroll
        for (int kk = 0; kk < BK; kk++) {
            float ra[TM], rb[TN];
            #pragma unroll
            for (int i = 0; i < TM; i++) ra[i] = As[kk][ty * TM + i];
            #pragma unroll
            for (int j = 0; j < TN; j++) rb[j] = Bs[kk][tx * TN + j];
            #pragma unroll
            for (int i = 0; i < TM; i++)
                #pragma unroll
                for (int j = 0; j < TN; j++)
                    acc[i][j] += ra[i] * rb[j];
        }
        __syncthreads();
    }
    #pragma unroll
    for (int i = 0; i < TM; i++) {
        int r = ridx[ty * TM + i];
        #pragma unroll
        for (int j = 0; j < TN; j += 4) {
            int c = col0 + tx * TN + j;
            float4 v = make_float4(acc[i][j], acc[i][j + 1], acc[i][j + 2], acc[i][j + 3]);
            *(float4*)(C + (size_t)r * N + c) = v;
        }
    }
}

// ------- fused head-W prep: limb split + fill dot, one pass over head_W ---------
// grid 4000 x 256: 8 warps/block, 1 column per warp. Lane handles d = k*32+lane,
// k = 0..7 (same index order as R13's fill_row -> identical g_fill bits; limb
// values elementwise identical to split2). Coalesced reads AND writes.
__global__ void prep_head_kernel(const float* __restrict__ head_W,
                                 const float* __restrict__ ln_b,
                                 const float* __restrict__ head_b,
                                 __nv_bfloat16* __restrict__ h0,
                                 __nv_bfloat16* __restrict__ h1) {
    __shared__ float lb[D];
    int tid = threadIdx.x;
    if (tid < D) lb[tid] = ln_b[tid];
    __syncthreads();
    int lane = tid & 31, w = tid >> 5;
    int c = blockIdx.x * 8 + w;
    if (c >= V) return;
    const float* wr = head_W + (size_t)c * D;
    float s = 0.f;
    #pragma unroll
    for (int k = 0; k < 8; k++) {
        int d = k * 32 + lane;
        float v = wr[d];
        __nv_bfloat16 a = __float2bfloat16(v);
        h0[(size_t)c * D + d] = a;
        h1[(size_t)c * D + d] = __float2bfloat16(v - __bfloat162float(a));
        s += lb[d] * v;
    }
    #pragma unroll
    for (int off = 16; off > 0; off >>= 1)
        s += __shfl_down_sync(0xFFFFFFFFu, s, off);
    if (lane == 0) g_fill[c] = s + head_b[c];
}

// ---------------- fill dropped-token output rows ----------------
__global__ void bias_fill_kernel(float* __restrict__ out) {
    int s = blockIdx.x;
    if (g_keepf[s]) return;
    float* dst = out + (size_t)s * V;
    for (int c = threadIdx.x * 4; c < V; c += 1024) {
        float4 v = *(const float4*)(g_fill + c);
        *(float4*)(dst + c) = v;
    }
}

// ---------------- embedding gather ----------------
__global__ void embed_kernel(const int* __restrict__ tokens,
                             const float* __restrict__ emb) {
    int s = blockIdx.x, d = threadIdx.x;
    g_x[s * D + d] = emb[(size_t)tokens[s] * D + d];
}

// ---------------- AstroNorm column stats (R9-exact order — order-locked) --------
__global__ void stats_kernel(const float* __restrict__ buffers,
                             const float* __restrict__ decays, int l) {
    int d = blockIdx.x, tid = threadIdx.x;
    float s = 0.f, s2 = 0.f;
    for (int i = tid; i < S; i += 256) {
        float v = g_x[i * D + d];
        s += v; s2 += v * v;
    }
    __shared__ float sh[256], sh2[256];
    sh[tid] = s; sh2[tid] = s2;
    __syncthreads();
    for (int off = 128; off > 0; off >>= 1) {
        if (tid < off) { sh[tid] += sh[tid + off]; sh2[tid] += sh2[tid + off]; }
        __syncthreads();
    }
    if (tid == 0) {
        float mu = sh[0] / (float)S;
        float var = (sh2[0] - (float)S * mu * mu) / (float)(S - 1);
        g_mu[d] = mu;
        g_istd[d] = rsqrtf(var + 1e-6f);
        float dec = decays[l];
        float nb = dec * buffers[l * D + d] + (1.f - dec) * mu;
        g_absnb[d] = fabsf(nb);
    }
}

// ---------------- apply AstroNorm + gate scores (R9-exact order) ----------------
__global__ void norm_score_kernel(const float* __restrict__ gate_w, int l) {
    int s = blockIdx.x, d = threadIdx.x;
    float v = g_x[s * D + d];
    float mu = g_mu[d];
    float v2 = (fabsf(v - mu) > g_absnb[d] ? mu : v) * g_istd[d];
    g_x[s * D + d] = v2;
    float p = v2 * gate_w[l * D + d];
    #pragma unroll
    for (int off = 16; off > 0; off >>= 1)
        p += __shfl_down_sync(0xFFFFFFFFu, p, off);
    __shared__ float w[8];
    if ((d & 31) == 0) w[d >> 5] = p;
    __syncthreads();
    if (d == 0) {
        float t = 0.f;
        #pragma unroll
        for (int i = 0; i < 8; i++) t += w[i];
        g_scores[s] = t;
    }
}

// ---------------- k-th largest: parallel order statistic ----------------
__global__ void select_kernel() {
    __shared__ float sc[S];
    __shared__ int sgt[32][8], sge[32][8];
    int tid = threadIdx.x;
    for (int i = tid; i < S; i += 256) sc[i] = g_scores[i];
    __syncthreads();
    int c = tid >> 3, part = tid & 7;
    float v = sc[blockIdx.x * 32 + c];
    int gt = 0, ge = 0;
    int j0 = part * 512;
    #pragma unroll 8
    for (int j = j0; j < j0 + 512; j++) {
        float u = sc[j];
        gt += (u > v);
        ge += (u >= v);
    }
    sgt[c][part] = gt; sge[c][part] = ge;
    __syncthreads();
    if (part == 0) {
        int GT = 0, GE = 0;
        #pragma unroll
        for (int p = 0; p < 8; p++) { GT += sgt[c][p]; GE += sge[c][p]; }
        if (GT < KGATE && GE >= KGATE) g_thr[0] = v;
    }
}

// --------- stable partition: kept token indices first, then dropped -------------
__global__ void partition_kernel() {   // 1 block x 1024 threads
    __shared__ int sc[1024];
    __shared__ int s_nk;
    int tid = threadIdx.x;
    float thr = g_thr[0];
    int base = tid * 4;
    int f[4], cnt = 0;
    #pragma unroll
    for (int j = 0; j < 4; j++) {
        f[j] = (g_scores[base + j] > thr) ? 1 : 0;
        cnt += f[j];
    }
    sc[tid] = cnt;
    __syncthreads();
    for (int off = 1; off < 1024; off <<= 1) {
        int v = (tid >= off) ? sc[tid - off] : 0;
        __syncthreads();
        sc[tid] += v;
        __syncthreads();
    }
    if (tid == 1023) s_nk = sc[1023];
    __syncthreads();
    int nk = s_nk;
    int kb = sc[tid] - cnt;
    #pragma unroll
    for (int j = 0; j < 4; j++) {
        int s = base + j;
        if (f[j]) { g_idx[kb] = s; g_keepf[s] = 1; kb++; }
        else      { g_idx[nk + (s - kb)] = s; g_keepf[s] = 0; }
    }
    if (tid == 0) g_nk[0] = nk;
}

// ---------- routing mask (float4 reduce, R9-exact) ----------------
__global__ void gate_mask_kernel(const float* __restrict__ gating_W,
                                 const float* __restrict__ gating_b, int l) {
    int s = blockIdx.x, d = threadIdx.x;
    bool keep = g_scores[s] > g_thr[0];
    float v = keep ? g_x[s * D + d] : 0.f;

    __shared__ float4 sh4[256];
    const float* W = gating_W + l * E * D;
    sh4[d] = make_float4(v * W[d], v * W[D + d], v * W[2 * D + d], v * W[3 * D + d]);
    __syncthreads();
    for (int off = 128; off > 0; off >>= 1) {
        if (d < off) {
            float4 x = sh4[d], y = sh4[d + off];
            sh4[d] = make_float4(x.x + y.x, x.y + y.y, x.z + y.z, x.w + y.w);
        }
        __syncthreads();
    }
    if (d == 0) {
        float gs[E] = { sh4[0].x + gating_b[l * E + 0],
                        sh4[0].y + gating_b[l * E + 1],
                        sh4[0].z + gating_b[l * E + 2],
                        sh4[0].w + gating_b[l * E + 3] };
        float best = gs[0]; int excl = 0;
        #pragma unroll
        for (int e = 1; e < E; e++)
            if (gs[e] <= best) { best = gs[e]; excl = e; }
        #pragma unroll
        for (int e = 0; e < E; e++)
            g_mask[s * E + e] = (e == excl) ? 0.f : 1.f;
    }
}

// ---------------- combine expert outputs with mask (R9-exact) ----------------
__global__ void combine_kernel(const float* __restrict__ exp_b, int l) {
    int s = blockIdx.x, o = threadIdx.x;
    float acc = 0.f;
    if (g_keepf[s]) {
        #pragma unroll
        for (int e = 0; e < E; e++) {
            float m = g_mask[s * E + e];
            acc += m * (g_y[(size_t)s * (E * D) + e * D + o] + exp_b[l * E * D + e * D + o]);
        }
    } else {
        #pragma unroll
        for (int e = 0; e < E; e++)
            acc += g_mask[s * E + e] * exp_b[l * E * D + e * D + o];
    }
    g_x[s * D + o] = acc;
}

// ---------------- final LayerNorm + 2-limb split for head ----------------
__global__ void ln_kernel(const float* __restrict__ g, const float* __restrict__ b) {
    int s = blockIdx.x, d = threadIdx.x;
    float v = g_x[s * D + d];
    __shared__ float sh[256];
    sh[d] = v;
    __syncthreads();
    for (int off = 128; off > 0; off >>= 1) {
        if (d < off) sh[d] += sh[d + off];
        __syncthreads();
    }
    float mean = sh[0] / (float)D;
    __syncthreads();
    float c = v - mean;
    sh[d] = c * c;
    __syncthreads();
    for (int off = 128; off > 0; off >>= 1) {
        if (d < off) sh[d] += sh[d + off];
        __syncthreads();
    }
    float var = sh[0] / (float)D;
    float y = c * rsqrtf(var + 1e-5f) * g[d] + b[d];
    __nv_bfloat16 h = __float2bfloat16(y);
    g_xs0[s * D + d] = h;
    g_xs1[s * D + d] = __float2bfloat16(y - __bfloat162float(h));
}

// ---------------- launch ----------------
extern "C" void kernel_launch(void* const* d_in, const int* in_sizes, int n_in,
                              void* d_out, int out_size) {
    const int*   tokens   = (const int*)  d_in[0];
    const float* emb      = (const float*)d_in[1];
    const float* buffers  = (const float*)d_in[2];
    const float* decays   = (const float*)d_in[3];
    const float* gate_w   = (const float*)d_in[4];
    const float* gating_W = (const float*)d_in[5];
    const float* gating_b = (const float*)d_in[6];
    const float* exp_W    = (const float*)d_in[7];
    const float* exp_b    = (const float*)d_in[8];
    const float* ln_g     = (const float*)d_in[9];
    const float* ln_b     = (const float*)d_in[10];
    const float* head_W   = (const float*)d_in[11];
    const float* head_b   = (const float*)d_in[12];
    float* out = (float*)d_out;

    float *xp, *yp;
    cudaGetSymbolAddress((void**)&xp, g_x);
    cudaGetSymbolAddress((void**)&yp, g_y);
    __nv_bfloat16 *xs0, *xs1, *wh0, *wh1;
    cudaGetSymbolAddress((void**)&xs0, g_xs0);
    cudaGetSymbolAddress((void**)&xs1, g_xs1);
    cudaGetSymbolAddress((void**)&wh0, g_wh0);
    cudaGetSymbolAddress((void**)&wh1, g_wh1);

    const int SMEMH = 2 * HSTAGE;   // 221184
    cudaFuncSetAttribute(head_gemm, cudaFuncAttributeMaxDynamicSharedMemorySize, SMEMH);

    // fused head-W prep: limbs + dropped-row fill dot, one pass over head_W
    prep_head_kernel<<<V / 8, 256>>>(head_W, ln_b, head_b, wh0, wh1);

    embed_kernel<<<S, 256>>>(tokens, emb);

    for (int l = 0; l < L; l++) {
        stats_kernel<<<D, 256>>>(buffers, decays, l);
        norm_score_kernel<<<S, 256>>>(gate_w, l);
        select_kernel<<<128, 256>>>();
        partition_kernel<<<1, 1024>>>();
        gate_mask_kernel<<<S, 256>>>(gating_W, gating_b, l);
        dim3 ge((E * D) / BN, S / BM);   // (8, 32); tiles past NK early-exit
        sgemm_gs<<<ge, 256>>>(xp, exp_W + (size_t)l * E * D * D, yp, S, E * D, D);
        combine_kernel<<<S, 256>>>(exp_b, l);
    }

    ln_kernel<<<S, 256>>>(ln_g, ln_b);

    dim3 gh(V / 256, S / 128);           // (125, 32); tiles past NK4 early-exit
    head_gemm<<<gh, 256, SMEMH>>>(xs0, xs1, wh0, wh1, out, head_b);
    bias_fill_kernel<<<S, 256>>>(out);
}